// round 6
// baseline (speedup 1.0000x reference)
#include <cuda_runtime.h>
#include <cuda_bf16.h>
#include <math.h>

#define Bb   4
#define Nn   2048
#define Ss   256
#define Cc   64
#define Hh   4
#define Dd   64
#define Ff   1024
#define ROWS (Bb*Nn)          // 8192

// ---------------- scratch (static device memory; no allocations) -------------
__device__ float g_sn[ROWS*Ss];            // LN'd scalar features (reused for both norms)
__device__ float g_vn[ROWS*Cc*3];          // eq-norm'd vector features (reused)
__device__ float g_q[ROWS*Ss];
__device__ float g_k[ROWS*Ss];
__device__ float g_vp[ROWS*Ss];            // value projection
__device__ float g_vmix[ROWS*Cc*3];        // vn @ Wvv, layout [row][e*3+x]
__device__ float g_attnmean[(size_t)Bb*Nn*Nn];  // 67 MB
__device__ float g_sattn[ROWS*Ss];
__device__ float g_vattn[ROWS*Cc*3];
__device__ float g_ffn[ROWS*Ff];

// ---------------- eq layernorm ----------------------------------------------
__global__ void __launch_bounds__(256) eqln_kernel(
    const float* __restrict__ sin, const float* __restrict__ vin,
    const float* __restrict__ g, const float* __restrict__ be,
    const float* __restrict__ vsc,
    float* __restrict__ sn, float* __restrict__ vn)
{
    long long row = blockIdx.x;
    int tid = threadIdx.x;
    __shared__ float redA[8], redB[8], norms[64], st[3];

    float x = sin[row*Ss + tid];
    float s1 = x, s2 = x*x;
    #pragma unroll
    for (int o = 16; o; o >>= 1) {
        s1 += __shfl_xor_sync(0xffffffffu, s1, o);
        s2 += __shfl_xor_sync(0xffffffffu, s2, o);
    }
    if ((tid & 31) == 0) { redA[tid>>5] = s1; redB[tid>>5] = s2; }

    if (tid < 64) {
        const float* vp = vin + row*192 + tid*3;
        float a = vp[0], b2 = vp[1], c = vp[2];
        norms[tid] = sqrtf(a*a + b2*b2 + c*c);
    }
    __syncthreads();
    if (tid == 0) {
        float A = 0.f, Bs2 = 0.f;
        #pragma unroll
        for (int w = 0; w < 8; w++) { A += redA[w]; Bs2 += redB[w]; }
        float mu  = A * (1.f/256.f);
        float var = Bs2 * (1.f/256.f) - mu*mu;
        st[0] = mu; st[1] = rsqrtf(var + 1e-5f);
        float t = 0.f;
        for (int c = 0; c < 64; c++) t += norms[c];
        st[2] = t * (1.f/64.f);
    }
    __syncthreads();
    sn[row*Ss + tid] = (x - st[0]) * st[1] * g[tid] + be[tid];
    if (tid < 192) {
        int c = tid / 3;
        vn[row*192 + tid] = vin[row*192 + tid] / (norms[c] + 1e-5f) * st[2] * vsc[c];
    }
}

// ---------------- generic tiled fp32 GEMM -----------------------------------
// C[m,n] = epi( A[m,:] @ W[:,n] + bias[n] (+ res[m,n]) )
// epi: 0 = none, 1 = exact gelu, 2 = add residual
__global__ void __launch_bounds__(256) gemm_kernel(
    const float* __restrict__ A, const float* __restrict__ W,
    const float* __restrict__ bias, const float* __restrict__ res,
    float* __restrict__ Cout,
    int M, int N, int K, int epi,
    long long sA, long long sW, long long sC)
{
    long long bz = blockIdx.z;
    A += bz * sA; W += bz * sW; Cout += bz * sC;
    const float* resp = res ? res + bz * sC : (const float*)0;

    __shared__ float As[16][68];
    __shared__ float Bs[16][64];

    int tid = threadIdx.x;
    int tx = tid & 15, ty = tid >> 4;
    int m0 = blockIdx.y * 64, n0 = blockIdx.x * 64;

    float acc[4][4] = {};

    for (int k0 = 0; k0 < K; k0 += 16) {
        #pragma unroll
        for (int r = 0; r < 4; r++) {
            int l = tid + r*256;
            int m = l >> 4, kk = l & 15;
            As[kk][m] = A[(long long)(m0+m)*K + k0 + kk];
        }
        #pragma unroll
        for (int r = 0; r < 4; r++) {
            int l = tid + r*256;
            int kk = l >> 6, n = l & 63;
            Bs[kk][n] = W[(long long)(k0+kk)*N + n0 + n];
        }
        __syncthreads();
        #pragma unroll
        for (int k = 0; k < 16; k++) {
            float4 af = *(const float4*)&As[k][ty*4];
            float4 bf = *(const float4*)&Bs[k][tx*4];
            float a[4] = {af.x, af.y, af.z, af.w};
            float b[4] = {bf.x, bf.y, bf.z, bf.w};
            #pragma unroll
            for (int i = 0; i < 4; i++)
                #pragma unroll
                for (int j = 0; j < 4; j++)
                    acc[i][j] += a[i]*b[j];
        }
        __syncthreads();
    }

    #pragma unroll
    for (int i = 0; i < 4; i++) {
        int m = m0 + ty*4 + i;
        #pragma unroll
        for (int j = 0; j < 4; j++) {
            int n = n0 + tx*4 + j;
            float cv = acc[i][j];
            if (bias) cv += bias[n];
            if (epi == 1) {
                cv = 0.5f * cv * (1.0f + erff(cv * 0.70710678118654752f));
            } else if (epi == 2) {
                cv += resp[(long long)m*N + n];
            }
            Cout[(long long)m*N + n] = cv;
        }
    }
}

// ---------------- small per-row channel mixes -------------------------------
__global__ void __launch_bounds__(192) vmix_kernel(
    const float* __restrict__ vn, const float* __restrict__ Wvv, float* __restrict__ out)
{
    long long row = blockIdx.x;
    int tid = threadIdx.x;
    __shared__ float vrow[192];
    vrow[tid] = vn[row*192 + tid];
    __syncthreads();
    int x = tid >> 6, e = tid & 63;
    float acc = 0.f;
    #pragma unroll 8
    for (int c = 0; c < 64; c++) acc += vrow[c*3 + x] * Wvv[c*64 + e];
    out[row*192 + e*3 + x] = acc;
}

__global__ void __launch_bounds__(192) vout_kernel(
    const float* __restrict__ vattn, const float* __restrict__ Wvo,
    const float* __restrict__ vin, float* __restrict__ outv)
{
    long long row = blockIdx.x;
    int tid = threadIdx.x;
    __shared__ float vrow[192];
    vrow[tid] = vattn[row*192 + tid];
    __syncthreads();
    int x = tid >> 6, e = tid & 63;
    float acc = 0.f;
    #pragma unroll 8
    for (int c = 0; c < 64; c++) acc += vrow[c*3 + x] * Wvo[c*64 + e];
    outv[row*192 + e*3 + x] = vin[row*192 + e*3 + x] + acc;
}

__global__ void __launch_bounds__(256) vffn_kernel(
    const float* __restrict__ vn, const float* __restrict__ Wfv1,
    const float* __restrict__ Wfv2, float* __restrict__ outv)
{
    long long row = blockIdx.x;
    int tid = threadIdx.x;
    __shared__ float vrow[192];
    __shared__ float t[3][256];
    if (tid < 192) vrow[tid] = vn[row*192 + tid];
    __syncthreads();
    #pragma unroll
    for (int x = 0; x < 3; x++) {
        float acc = 0.f;
        #pragma unroll 8
        for (int c = 0; c < 64; c++) acc += vrow[c*3 + x] * Wfv1[c*256 + tid];
        t[x][tid] = acc;
    }
    __syncthreads();
    if (tid < 192) {
        int x = tid >> 6, c = tid & 63;
        float acc = 0.f;
        #pragma unroll 8
        for (int h = 0; h < 256; h++) acc += t[x][h] * Wfv2[h*64 + c];
        outv[row*192 + c*3 + x] += acc;
    }
}

// ---------------- fused attention (2-pass flash, all heads per CTA) ----------
// smem floats: q 8192 | kT 8448 | vs 8192 | probs 4096 | posm 128 | posi 128 | linv 128
#define ATTN_SMEM_FLOATS (8192 + 8448 + 8192 + 4096 + 128 + 128 + 128)

__global__ void __launch_bounds__(256) attn_kernel(
    const float* __restrict__ qg, const float* __restrict__ kg,
    const float* __restrict__ vg, const float* __restrict__ pos,
    const float* __restrict__ wdist, const float* __restrict__ bdist,
    float* __restrict__ attnmean, float* __restrict__ sattn)
{
    extern __shared__ float sm[];
    float* q_s   = sm;                   // [32][256]
    float* kT    = q_s  + 8192;          // [256][33]
    float* vs_s  = kT   + 8448;          // [32][256]
    float* probs = vs_s + 8192;          // [4][32][32]
    float* posm  = probs + 4096;         // [32][4] : x,y,z,|p|^2
    float* posi  = posm + 128;
    float* linv  = posi + 128;           // [4][32]

    int b  = blockIdx.y;
    int n0 = blockIdx.x * 32;
    int tid = threadIdx.x, lane = tid & 31, wrp = tid >> 5;

    const long long bofs = (long long)b * Nn;

    for (int idx = tid; idx < 8192; idx += 256)
        q_s[idx] = qg[(bofs + n0 + (idx>>8))*Ss + (idx & 255)];
    if (tid < 32) {
        const float* pp = pos + (bofs + n0 + tid)*3;
        float a = pp[0], b2 = pp[1], c = pp[2];
        posi[tid*4+0] = a; posi[tid*4+1] = b2; posi[tid*4+2] = c;
        posi[tid*4+3] = a*a + b2*b2 + c*c;
    }
    float w_h[4], b_h[4];
    #pragma unroll
    for (int h = 0; h < 4; h++) { w_h[h] = wdist[h]; b_h[h] = bdist[h]; }

    // ---------- pass 1: per-head softmax denominators ----------
    float lsum[16];
    #pragma unroll
    for (int t = 0; t < 16; t++) lsum[t] = 0.f;

    for (int mt = 0; mt < 64; mt++) {
        int m0 = mt * 32;
        __syncthreads();
        for (int idx = tid; idx < 8192; idx += 256)
            kT[(idx & 255)*33 + (idx>>8)] = kg[(bofs + m0 + (idx>>8))*Ss + (idx & 255)];
        if (tid < 32) {
            const float* pp = pos + (bofs + m0 + tid)*3;
            float a = pp[0], b2 = pp[1], c = pp[2];
            posm[tid*4+0] = a; posm[tid*4+1] = b2; posm[tid*4+2] = c;
            posm[tid*4+3] = a*a + b2*b2 + c*c;
        }
        __syncthreads();

        float px = posm[lane*4], py = posm[lane*4+1], pz = posm[lane*4+2], pq = posm[lane*4+3];
        float dist4[4];
        #pragma unroll
        for (int il = 0; il < 4; il++) {
            int i = wrp + il*8;
            float d2 = posi[i*4+3] + pq
                     - 2.f*(posi[i*4]*px + posi[i*4+1]*py + posi[i*4+2]*pz);
            dist4[il] = sqrtf(fmaxf(d2, 1e-12f));
        }
        #pragma unroll
        for (int h = 0; h < 4; h++) {
            float a0=0.f, a1=0.f, a2=0.f, a3=0.f;
            const float* kc = &kT[(h*64)*33 + lane];
            const float* q0 = &q_s[(wrp+ 0)*256 + h*64];
            const float* q1 = &q_s[(wrp+ 8)*256 + h*64];
            const float* q2 = &q_s[(wrp+16)*256 + h*64];
            const float* q3 = &q_s[(wrp+24)*256 + h*64];
            #pragma unroll
            for (int dd = 0; dd < 64; dd++) {
                float kv = kc[dd*33];
                a0 += q0[dd]*kv; a1 += q1[dd]*kv; a2 += q2[dd]*kv; a3 += q3[dd]*kv;
            }
            float wh = w_h[h], bh = b_h[h];
            #pragma unroll
            for (int il = 0; il < 4; il++) {
                float av = (il==0)?a0:((il==1)?a1:((il==2)?a2:a3));
                float sx = dist4[il]*wh + bh;
                float sp = fmaxf(sx, 0.f) + log1pf(__expf(-fabsf(sx)));
                lsum[il*4+h] += __expf(av*0.125f - sp);
            }
        }
    }
    #pragma unroll
    for (int t = 0; t < 16; t++) {
        float v = lsum[t];
        #pragma unroll
        for (int o = 16; o; o >>= 1) v += __shfl_xor_sync(0xffffffffu, v, o);
        if (lane == 0) {
            int il = t >> 2, h = t & 3;
            linv[h*32 + wrp + il*8] = 1.f / v;
        }
    }
    __syncthreads();

    // ---------- pass 2: normalized probs, attn_mean, PV accumulation ----------
    float accS[32];
    #pragma unroll
    for (int i = 0; i < 32; i++) accS[i] = 0.f;
    int col  = tid;
    int hcol = col >> 6;

    for (int mt = 0; mt < 64; mt++) {
        int m0 = mt * 32;
        __syncthreads();
        for (int idx = tid; idx < 8192; idx += 256) {
            kT[(idx & 255)*33 + (idx>>8)] = kg[(bofs + m0 + (idx>>8))*Ss + (idx & 255)];
            vs_s[idx] = vg[(bofs + m0 + (idx>>8))*Ss + (idx & 255)];
        }
        if (tid < 32) {
            const float* pp = pos + (bofs + m0 + tid)*3;
            float a = pp[0], b2 = pp[1], c = pp[2];
            posm[tid*4+0] = a; posm[tid*4+1] = b2; posm[tid*4+2] = c;
            posm[tid*4+3] = a*a + b2*b2 + c*c;
        }
        __syncthreads();

        float px = posm[lane*4], py = posm[lane*4+1], pz = posm[lane*4+2], pq = posm[lane*4+3];
        float dist4[4];
        #pragma unroll
        for (int il = 0; il < 4; il++) {
            int i = wrp + il*8;
            float d2 = posi[i*4+3] + pq
                     - 2.f*(posi[i*4]*px + posi[i*4+1]*py + posi[i*4+2]*pz);
            dist4[il] = sqrtf(fmaxf(d2, 1e-12f));
        }
        #pragma unroll
        for (int h = 0; h < 4; h++) {
            float a0=0.f, a1=0.f, a2=0.f, a3=0.f;
            const float* kc = &kT[(h*64)*33 + lane];
            const float* q0 = &q_s[(wrp+ 0)*256 + h*64];
            const float* q1 = &q_s[(wrp+ 8)*256 + h*64];
            const float* q2 = &q_s[(wrp+16)*256 + h*64];
            const float* q3 = &q_s[(wrp+24)*256 + h*64];
            #pragma unroll
            for (int dd = 0; dd < 64; dd++) {
                float kv = kc[dd*33];
                a0 += q0[dd]*kv; a1 += q1[dd]*kv; a2 += q2[dd]*kv; a3 += q3[dd]*kv;
            }
            float wh = w_h[h], bh = b_h[h];
            #pragma unroll
            for (int il = 0; il < 4; il++) {
                float av = (il==0)?a0:((il==1)?a1:((il==2)?a2:a3));
                int i = wrp + il*8;
                float sx = dist4[il]*wh + bh;
                float sp = fmaxf(sx, 0.f) + log1pf(__expf(-fabsf(sx)));
                float p = __expf(av*0.125f - sp) * linv[h*32 + i];
                probs[(h*32 + i)*32 + lane] = p;
            }
        }
        __syncthreads();

        // attn_mean (head average), coalesced over j
        for (int e = tid; e < 1024; e += 256) {
            int i = e >> 5, j = e & 31;
            float pm = 0.25f * (probs[i*32+j] + probs[(32+i)*32+j]
                              + probs[(64+i)*32+j] + probs[(96+i)*32+j]);
            attnmean[(bofs + n0 + i)*(long long)Nn + m0 + j] = pm;
        }

        // PV accumulation: thread owns one output column, 32 rows
        #pragma unroll 4
        for (int j = 0; j < 32; j++) {
            float vj = vs_s[j*256 + col];
            const float* pr = &probs[hcol*1024 + j];
            #pragma unroll
            for (int i = 0; i < 32; i++) accS[i] += pr[i*32] * vj;
        }
    }
    #pragma unroll
    for (int i = 0; i < 32; i++)
        sattn[(bofs + n0 + i)*Ss + col] = accS[i];
}

// ---------------- launch ------------------------------------------------------
extern "C" void kernel_launch(void* const* d_in, const int* in_sizes, int n_in,
                              void* d_out, int out_size)
{
    const float* s_in  = (const float*)d_in[0];
    const float* v_in  = (const float*)d_in[1];
    const float* pos   = (const float*)d_in[2];
    const float* Wq    = (const float*)d_in[3];
    const float* bq    = (const float*)d_in[4];
    const float* Wk    = (const float*)d_in[5];
    const float* bk    = (const float*)d_in[6];
    const float* Wv    = (const float*)d_in[7];
    const float* bv    = (const float*)d_in[8];
    const float* Wo    = (const float*)d_in[9];
    const float* bo    = (const float*)d_in[10];
    const float* wdist = (const float*)d_in[11];
    const float* bdist = (const float*)d_in[12];
    const float* Wvv   = (const float*)d_in[13];
    const float* Wvo   = (const float*)d_in[14];
    const float* g1    = (const float*)d_in[15];
    const float* be1   = (const float*)d_in[16];
    const float* vs1   = (const float*)d_in[17];
    const float* g2    = (const float*)d_in[18];
    const float* be2   = (const float*)d_in[19];
    const float* vs2   = (const float*)d_in[20];
    const float* Wf1   = (const float*)d_in[21];
    const float* bf1   = (const float*)d_in[22];
    const float* Wf2   = (const float*)d_in[23];
    const float* bf2   = (const float*)d_in[24];
    const float* Wfv1  = (const float*)d_in[25];
    const float* Wfv2  = (const float*)d_in[26];

    float* out_s = (float*)d_out;
    float* out_v = out_s + (size_t)ROWS*Ss;

    void *p_sn, *p_vn, *p_q, *p_k, *p_vp, *p_vmix, *p_am, *p_sa, *p_va, *p_ffn;
    cudaGetSymbolAddress(&p_sn, g_sn);
    cudaGetSymbolAddress(&p_vn, g_vn);
    cudaGetSymbolAddress(&p_q,  g_q);
    cudaGetSymbolAddress(&p_k,  g_k);
    cudaGetSymbolAddress(&p_vp, g_vp);
    cudaGetSymbolAddress(&p_vmix, g_vmix);
    cudaGetSymbolAddress(&p_am, g_attnmean);
    cudaGetSymbolAddress(&p_sa, g_sattn);
    cudaGetSymbolAddress(&p_va, g_vattn);
    cudaGetSymbolAddress(&p_ffn, g_ffn);
    float* sn   = (float*)p_sn;   float* vn   = (float*)p_vn;
    float* q    = (float*)p_q;    float* k    = (float*)p_k;
    float* vp   = (float*)p_vp;   float* vmix = (float*)p_vmix;
    float* am   = (float*)p_am;   float* sa   = (float*)p_sa;
    float* va   = (float*)p_va;   float* ffn  = (float*)p_ffn;

    const int attn_smem = ATTN_SMEM_FLOATS * 4;
    cudaFuncSetAttribute(attn_kernel, cudaFuncAttributeMaxDynamicSharedMemorySize, attn_smem);

    // 1) eq-LN #1
    eqln_kernel<<<ROWS, 256>>>(s_in, v_in, g1, be1, vs1, sn, vn);

    // 2) QKV projections
    dim3 gproj(Ss/64, ROWS/64, 1);
    gemm_kernel<<<gproj, 256>>>(sn, Wq, bq, nullptr, q,  ROWS, Ss, Ss, 0, 0, 0, 0);
    gemm_kernel<<<gproj, 256>>>(sn, Wk, bk, nullptr, k,  ROWS, Ss, Ss, 0, 0, 0, 0);
    gemm_kernel<<<gproj, 256>>>(sn, Wv, bv, nullptr, vp, ROWS, Ss, Ss, 0, 0, 0, 0);

    // 3) vector channel mix (vn @ Wvv)
    vmix_kernel<<<ROWS, 192>>>(vn, Wvv, vmix);

    // 4) fused attention: writes g_sattn + g_attnmean
    attn_kernel<<<dim3(Nn/32, Bb), 256, attn_smem>>>(q, k, vp, pos, wdist, bdist, am, sa);

    // 5) out_s = s_in + sattn @ Wo + bo
    gemm_kernel<<<gproj, 256>>>(sa, Wo, bo, s_in, out_s, ROWS, Ss, Ss, 2, 0, 0, 0);

    // 6) v_attn_raw = attn_mean @ vmix  (batched over B)
    gemm_kernel<<<dim3(192/64, Nn/64, Bb), 256>>>(
        am, vmix, nullptr, nullptr, va,
        Nn, 192, Nn, 0,
        (long long)Nn*Nn, (long long)Nn*192, (long long)Nn*192);

    // 7) out_v = v_in + v_attn_raw @ Wvo
    vout_kernel<<<ROWS, 192>>>(va, Wvo, v_in, out_v);

    // 8) eq-LN #2 (on updated s, v)
    eqln_kernel<<<ROWS, 256>>>(out_s, out_v, g2, be2, vs2, sn, vn);

    // 9) FFN
    gemm_kernel<<<dim3(Ff/64, ROWS/64, 1), 256>>>(sn, Wf1, bf1, nullptr, ffn, ROWS, Ff, Ss, 1, 0, 0, 0);
    gemm_kernel<<<dim3(Ss/64, ROWS/64, 1), 256>>>(ffn, Wf2, bf2, out_s, out_s, ROWS, Ss, Ff, 2, 0, 0, 0);

    // 10) vector FFN
    vffn_kernel<<<ROWS, 256>>>(vn, Wfv1, Wfv2, out_v);
}

// round 7
// speedup vs baseline: 1.0047x; 1.0047x over previous
#include <cuda_runtime.h>
#include <cuda_bf16.h>
#include <math.h>

#define Bb   4
#define Nn   2048
#define Ss   256
#define Cc   64
#define Hh   4
#define Dd   64
#define Ff   1024
#define ROWS (Bb*Nn)          // 8192

// ---------------- scratch (static device memory; no allocations) -------------
__device__ float g_sn[ROWS*Ss];            // LN'd scalar features (reused for both norms)
__device__ float g_vn[ROWS*Cc*3];          // eq-norm'd vector features (reused)
__device__ float g_q[ROWS*Ss];
__device__ float g_k[ROWS*Ss];
__device__ float g_vp[ROWS*Ss];            // value projection
__device__ float g_vmix[ROWS*Cc*3];        // vn @ Wvv, layout [row][e*3+x]
__device__ float g_attnmean[(size_t)Bb*Nn*Nn];  // 67 MB
__device__ float g_sattn[ROWS*Ss];
__device__ float g_vattn[ROWS*Cc*3];
__device__ float g_ffn[ROWS*Ff];

// ---------------- eq layernorm ----------------------------------------------
__global__ void __launch_bounds__(256) eqln_kernel(
    const float* __restrict__ sin, const float* __restrict__ vin,
    const float* __restrict__ g, const float* __restrict__ be,
    const float* __restrict__ vsc,
    float* __restrict__ sn, float* __restrict__ vn)
{
    long long row = blockIdx.x;
    int tid = threadIdx.x;
    __shared__ float redA[8], redB[8], norms[64], st[3];

    float x = sin[row*Ss + tid];
    float s1 = x, s2 = x*x;
    #pragma unroll
    for (int o = 16; o; o >>= 1) {
        s1 += __shfl_xor_sync(0xffffffffu, s1, o);
        s2 += __shfl_xor_sync(0xffffffffu, s2, o);
    }
    if ((tid & 31) == 0) { redA[tid>>5] = s1; redB[tid>>5] = s2; }

    if (tid < 64) {
        const float* vp = vin + row*192 + tid*3;
        float a = vp[0], b2 = vp[1], c = vp[2];
        norms[tid] = sqrtf(a*a + b2*b2 + c*c);
    }
    __syncthreads();
    if (tid == 0) {
        float A = 0.f, Bs2 = 0.f;
        #pragma unroll
        for (int w = 0; w < 8; w++) { A += redA[w]; Bs2 += redB[w]; }
        float mu  = A * (1.f/256.f);
        float var = Bs2 * (1.f/256.f) - mu*mu;
        st[0] = mu; st[1] = rsqrtf(var + 1e-5f);
        float t = 0.f;
        for (int c = 0; c < 64; c++) t += norms[c];
        st[2] = t * (1.f/64.f);
    }
    __syncthreads();
    sn[row*Ss + tid] = (x - st[0]) * st[1] * g[tid] + be[tid];
    if (tid < 192) {
        int c = tid / 3;
        vn[row*192 + tid] = vin[row*192 + tid] / (norms[c] + 1e-5f) * st[2] * vsc[c];
    }
}

// ---------------- generic tiled fp32 GEMM -----------------------------------
// C[m,n] = epi( A[m,:] @ W[:,n] + bias[n] (+ res[m,n]) )
// epi: 0 = none, 1 = exact gelu, 2 = add residual
__global__ void __launch_bounds__(256) gemm_kernel(
    const float* __restrict__ A, const float* __restrict__ W,
    const float* __restrict__ bias, const float* __restrict__ res,
    float* __restrict__ Cout,
    int M, int N, int K, int epi,
    long long sA, long long sW, long long sC)
{
    long long bz = blockIdx.z;
    A += bz * sA; W += bz * sW; Cout += bz * sC;
    const float* resp = res ? res + bz * sC : (const float*)0;

    __shared__ float As[16][68];
    __shared__ float Bs[16][64];

    int tid = threadIdx.x;
    int tx = tid & 15, ty = tid >> 4;
    int m0 = blockIdx.y * 64, n0 = blockIdx.x * 64;

    float acc[4][4] = {};

    for (int k0 = 0; k0 < K; k0 += 16) {
        #pragma unroll
        for (int r = 0; r < 4; r++) {
            int l = tid + r*256;
            int m = l >> 4, kk = l & 15;
            As[kk][m] = A[(long long)(m0+m)*K + k0 + kk];
        }
        #pragma unroll
        for (int r = 0; r < 4; r++) {
            int l = tid + r*256;
            int kk = l >> 6, n = l & 63;
            Bs[kk][n] = W[(long long)(k0+kk)*N + n0 + n];
        }
        __syncthreads();
        #pragma unroll
        for (int k = 0; k < 16; k++) {
            float4 af = *(const float4*)&As[k][ty*4];
            float4 bf = *(const float4*)&Bs[k][tx*4];
            float a[4] = {af.x, af.y, af.z, af.w};
            float b[4] = {bf.x, bf.y, bf.z, bf.w};
            #pragma unroll
            for (int i = 0; i < 4; i++)
                #pragma unroll
                for (int j = 0; j < 4; j++)
                    acc[i][j] += a[i]*b[j];
        }
        __syncthreads();
    }

    #pragma unroll
    for (int i = 0; i < 4; i++) {
        int m = m0 + ty*4 + i;
        #pragma unroll
        for (int j = 0; j < 4; j++) {
            int n = n0 + tx*4 + j;
            float cv = acc[i][j];
            if (bias) cv += bias[n];
            if (epi == 1) {
                cv = 0.5f * cv * (1.0f + erff(cv * 0.70710678118654752f));
            } else if (epi == 2) {
                cv += resp[(long long)m*N + n];
            }
            Cout[(long long)m*N + n] = cv;
        }
    }
}

// ---------------- small per-row channel mixes -------------------------------
__global__ void __launch_bounds__(192) vmix_kernel(
    const float* __restrict__ vn, const float* __restrict__ Wvv, float* __restrict__ out)
{
    long long row = blockIdx.x;
    int tid = threadIdx.x;
    __shared__ float vrow[192];
    vrow[tid] = vn[row*192 + tid];
    __syncthreads();
    int x = tid >> 6, e = tid & 63;
    float acc = 0.f;
    #pragma unroll 8
    for (int c = 0; c < 64; c++) acc += vrow[c*3 + x] * Wvv[c*64 + e];
    out[row*192 + e*3 + x] = acc;
}

__global__ void __launch_bounds__(192) vout_kernel(
    const float* __restrict__ vattn, const float* __restrict__ Wvo,
    const float* __restrict__ vin, float* __restrict__ outv)
{
    long long row = blockIdx.x;
    int tid = threadIdx.x;
    __shared__ float vrow[192];
    vrow[tid] = vattn[row*192 + tid];
    __syncthreads();
    int x = tid >> 6, e = tid & 63;
    float acc = 0.f;
    #pragma unroll 8
    for (int c = 0; c < 64; c++) acc += vrow[c*3 + x] * Wvo[c*64 + e];
    outv[row*192 + e*3 + x] = vin[row*192 + e*3 + x] + acc;
}

__global__ void __launch_bounds__(256) vffn_kernel(
    const float* __restrict__ vn, const float* __restrict__ Wfv1,
    const float* __restrict__ Wfv2, float* __restrict__ outv)
{
    long long row = blockIdx.x;
    int tid = threadIdx.x;
    __shared__ float vrow[192];
    __shared__ float t[3][256];
    if (tid < 192) vrow[tid] = vn[row*192 + tid];
    __syncthreads();
    #pragma unroll
    for (int x = 0; x < 3; x++) {
        float acc = 0.f;
        #pragma unroll 8
        for (int c = 0; c < 64; c++) acc += vrow[c*3 + x] * Wfv1[c*256 + tid];
        t[x][tid] = acc;
    }
    __syncthreads();
    if (tid < 192) {
        int x = tid >> 6, c = tid & 63;
        float acc = 0.f;
        #pragma unroll 8
        for (int h = 0; h < 256; h++) acc += t[x][h] * Wfv2[h*64 + c];
        outv[row*192 + c*3 + x] += acc;
    }
}

// ---------------- fused attention (2-pass flash, all heads per CTA) ----------
// smem floats: q 8192 | kT 8448 | vs 8192 | probs 4096 | posm 128 | posi 128 | linv 128
#define ATTN_SMEM_FLOATS (8192 + 8448 + 8192 + 4096 + 128 + 128 + 128)

__global__ void __launch_bounds__(256) attn_kernel(
    const float* __restrict__ qg, const float* __restrict__ kg,
    const float* __restrict__ vg, const float* __restrict__ pos,
    const float* __restrict__ wdist, const float* __restrict__ bdist,
    float* __restrict__ attnmean, float* __restrict__ sattn)
{
    extern __shared__ float sm[];
    float* q_s   = sm;                   // [32][256]
    float* kT    = q_s  + 8192;          // [256][33]
    float* vs_s  = kT   + 8448;          // [32][256]
    float* probs = vs_s + 8192;          // [4][32][32]
    float* posm  = probs + 4096;         // [32][4] : x,y,z,|p|^2
    float* posi  = posm + 128;
    float* linv  = posi + 128;           // [4][32]

    int b  = blockIdx.y;
    int n0 = blockIdx.x * 32;
    int tid = threadIdx.x, lane = tid & 31, wrp = tid >> 5;

    const long long bofs = (long long)b * Nn;

    for (int idx = tid; idx < 8192; idx += 256)
        q_s[idx] = qg[(bofs + n0 + (idx>>8))*Ss + (idx & 255)];
    if (tid < 32) {
        const float* pp = pos + (bofs + n0 + tid)*3;
        float a = pp[0], b2 = pp[1], c = pp[2];
        posi[tid*4+0] = a; posi[tid*4+1] = b2; posi[tid*4+2] = c;
        posi[tid*4+3] = a*a + b2*b2 + c*c;
    }
    float w_h[4], b_h[4];
    #pragma unroll
    for (int h = 0; h < 4; h++) { w_h[h] = wdist[h]; b_h[h] = bdist[h]; }

    // ---------- pass 1: per-head softmax denominators ----------
    float lsum[16];
    #pragma unroll
    for (int t = 0; t < 16; t++) lsum[t] = 0.f;

    for (int mt = 0; mt < 64; mt++) {
        int m0 = mt * 32;
        __syncthreads();
        for (int idx = tid; idx < 8192; idx += 256)
            kT[(idx & 255)*33 + (idx>>8)] = kg[(bofs + m0 + (idx>>8))*Ss + (idx & 255)];
        if (tid < 32) {
            const float* pp = pos + (bofs + m0 + tid)*3;
            float a = pp[0], b2 = pp[1], c = pp[2];
            posm[tid*4+0] = a; posm[tid*4+1] = b2; posm[tid*4+2] = c;
            posm[tid*4+3] = a*a + b2*b2 + c*c;
        }
        __syncthreads();

        float px = posm[lane*4], py = posm[lane*4+1], pz = posm[lane*4+2], pq = posm[lane*4+3];
        float dist4[4];
        #pragma unroll
        for (int il = 0; il < 4; il++) {
            int i = wrp + il*8;
            float d2 = posi[i*4+3] + pq
                     - 2.f*(posi[i*4]*px + posi[i*4+1]*py + posi[i*4+2]*pz);
            dist4[il] = sqrtf(fmaxf(d2, 1e-12f));
        }
        #pragma unroll
        for (int h = 0; h < 4; h++) {
            float a0=0.f, a1=0.f, a2=0.f, a3=0.f;
            const float* kc = &kT[(h*64)*33 + lane];
            const float* q0 = &q_s[(wrp+ 0)*256 + h*64];
            const float* q1 = &q_s[(wrp+ 8)*256 + h*64];
            const float* q2 = &q_s[(wrp+16)*256 + h*64];
            const float* q3 = &q_s[(wrp+24)*256 + h*64];
            #pragma unroll
            for (int dd = 0; dd < 64; dd++) {
                float kv = kc[dd*33];
                a0 += q0[dd]*kv; a1 += q1[dd]*kv; a2 += q2[dd]*kv; a3 += q3[dd]*kv;
            }
            float wh = w_h[h], bh = b_h[h];
            #pragma unroll
            for (int il = 0; il < 4; il++) {
                float av = (il==0)?a0:((il==1)?a1:((il==2)?a2:a3));
                float sx = dist4[il]*wh + bh;
                float sp = fmaxf(sx, 0.f) + log1pf(__expf(-fabsf(sx)));
                lsum[il*4+h] += __expf(av*0.125f - sp);
            }
        }
    }
    #pragma unroll
    for (int t = 0; t < 16; t++) {
        float v = lsum[t];
        #pragma unroll
        for (int o = 16; o; o >>= 1) v += __shfl_xor_sync(0xffffffffu, v, o);
        if (lane == 0) {
            int il = t >> 2, h = t & 3;
            linv[h*32 + wrp + il*8] = 1.f / v;
        }
    }
    __syncthreads();

    // ---------- pass 2: normalized probs, attn_mean, PV accumulation ----------
    float accS[32];
    #pragma unroll
    for (int i = 0; i < 32; i++) accS[i] = 0.f;
    int col  = tid;
    int hcol = col >> 6;

    for (int mt = 0; mt < 64; mt++) {
        int m0 = mt * 32;
        __syncthreads();
        for (int idx = tid; idx < 8192; idx += 256) {
            kT[(idx & 255)*33 + (idx>>8)] = kg[(bofs + m0 + (idx>>8))*Ss + (idx & 255)];
            vs_s[idx] = vg[(bofs + m0 + (idx>>8))*Ss + (idx & 255)];
        }
        if (tid < 32) {
            const float* pp = pos + (bofs + m0 + tid)*3;
            float a = pp[0], b2 = pp[1], c = pp[2];
            posm[tid*4+0] = a; posm[tid*4+1] = b2; posm[tid*4+2] = c;
            posm[tid*4+3] = a*a + b2*b2 + c*c;
        }
        __syncthreads();

        float px = posm[lane*4], py = posm[lane*4+1], pz = posm[lane*4+2], pq = posm[lane*4+3];
        float dist4[4];
        #pragma unroll
        for (int il = 0; il < 4; il++) {
            int i = wrp + il*8;
            float d2 = posi[i*4+3] + pq
                     - 2.f*(posi[i*4]*px + posi[i*4+1]*py + posi[i*4+2]*pz);
            dist4[il] = sqrtf(fmaxf(d2, 1e-12f));
        }
        #pragma unroll
        for (int h = 0; h < 4; h++) {
            float a0=0.f, a1=0.f, a2=0.f, a3=0.f;
            const float* kc = &kT[(h*64)*33 + lane];
            const float* q0 = &q_s[(wrp+ 0)*256 + h*64];
            const float* q1 = &q_s[(wrp+ 8)*256 + h*64];
            const float* q2 = &q_s[(wrp+16)*256 + h*64];
            const float* q3 = &q_s[(wrp+24)*256 + h*64];
            #pragma unroll
            for (int dd = 0; dd < 64; dd++) {
                float kv = kc[dd*33];
                a0 += q0[dd]*kv; a1 += q1[dd]*kv; a2 += q2[dd]*kv; a3 += q3[dd]*kv;
            }
            float wh = w_h[h], bh = b_h[h];
            #pragma unroll
            for (int il = 0; il < 4; il++) {
                float av = (il==0)?a0:((il==1)?a1:((il==2)?a2:a3));
                int i = wrp + il*8;
                float sx = dist4[il]*wh + bh;
                float sp = fmaxf(sx, 0.f) + log1pf(__expf(-fabsf(sx)));
                float p = __expf(av*0.125f - sp) * linv[h*32 + i];
                probs[(h*32 + i)*32 + lane] = p;
            }
        }
        __syncthreads();

        // attn_mean (head average), coalesced over j
        for (int e = tid; e < 1024; e += 256) {
            int i = e >> 5, j = e & 31;
            float pm = 0.25f * (probs[i*32+j] + probs[(32+i)*32+j]
                              + probs[(64+i)*32+j] + probs[(96+i)*32+j]);
            attnmean[(bofs + n0 + i)*(long long)Nn + m0 + j] = pm;
        }

        // PV accumulation: thread owns one output column, 32 rows
        #pragma unroll 4
        for (int j = 0; j < 32; j++) {
            float vj = vs_s[j*256 + col];
            const float* pr = &probs[hcol*1024 + j];
            #pragma unroll
            for (int i = 0; i < 32; i++) accS[i] += pr[i*32] * vj;
        }
    }
    #pragma unroll
    for (int i = 0; i < 32; i++)
        sattn[(bofs + n0 + i)*Ss + col] = accS[i];
}

// ---------------- launch ------------------------------------------------------
extern "C" void kernel_launch(void* const* d_in, const int* in_sizes, int n_in,
                              void* d_out, int out_size)
{
    const float* s_in  = (const float*)d_in[0];
    const float* v_in  = (const float*)d_in[1];
    const float* pos   = (const float*)d_in[2];
    const float* Wq    = (const float*)d_in[3];
    const float* bq    = (const float*)d_in[4];
    const float* Wk    = (const float*)d_in[5];
    const float* bk    = (const float*)d_in[6];
    const float* Wv    = (const float*)d_in[7];
    const float* bv    = (const float*)d_in[8];
    const float* Wo    = (const float*)d_in[9];
    const float* bo    = (const float*)d_in[10];
    const float* wdist = (const float*)d_in[11];
    const float* bdist = (const float*)d_in[12];
    const float* Wvv   = (const float*)d_in[13];
    const float* Wvo   = (const float*)d_in[14];
    const float* g1    = (const float*)d_in[15];
    const float* be1   = (const float*)d_in[16];
    const float* vs1   = (const float*)d_in[17];
    const float* g2    = (const float*)d_in[18];
    const float* be2   = (const float*)d_in[19];
    const float* vs2   = (const float*)d_in[20];
    const float* Wf1   = (const float*)d_in[21];
    const float* bf1   = (const float*)d_in[22];
    const float* Wf2   = (const float*)d_in[23];
    const float* bf2   = (const float*)d_in[24];
    const float* Wfv1  = (const float*)d_in[25];
    const float* Wfv2  = (const float*)d_in[26];

    float* out_s = (float*)d_out;
    float* out_v = out_s + (size_t)ROWS*Ss;

    void *p_sn, *p_vn, *p_q, *p_k, *p_vp, *p_vmix, *p_am, *p_sa, *p_va, *p_ffn;
    cudaGetSymbolAddress(&p_sn, g_sn);
    cudaGetSymbolAddress(&p_vn, g_vn);
    cudaGetSymbolAddress(&p_q,  g_q);
    cudaGetSymbolAddress(&p_k,  g_k);
    cudaGetSymbolAddress(&p_vp, g_vp);
    cudaGetSymbolAddress(&p_vmix, g_vmix);
    cudaGetSymbolAddress(&p_am, g_attnmean);
    cudaGetSymbolAddress(&p_sa, g_sattn);
    cudaGetSymbolAddress(&p_va, g_vattn);
    cudaGetSymbolAddress(&p_ffn, g_ffn);
    float* sn   = (float*)p_sn;   float* vn   = (float*)p_vn;
    float* q    = (float*)p_q;    float* k    = (float*)p_k;
    float* vp   = (float*)p_vp;   float* vmix = (float*)p_vmix;
    float* am   = (float*)p_am;   float* sa   = (float*)p_sa;
    float* va   = (float*)p_va;   float* ffn  = (float*)p_ffn;

    const int attn_smem = ATTN_SMEM_FLOATS * 4;
    cudaFuncSetAttribute(attn_kernel, cudaFuncAttributeMaxDynamicSharedMemorySize, attn_smem);

    // 1) eq-LN #1
    eqln_kernel<<<ROWS, 256>>>(s_in, v_in, g1, be1, vs1, sn, vn);

    // 2) QKV projections
    dim3 gproj(Ss/64, ROWS/64, 1);
    gemm_kernel<<<gproj, 256>>>(sn, Wq, bq, nullptr, q,  ROWS, Ss, Ss, 0, 0, 0, 0);
    gemm_kernel<<<gproj, 256>>>(sn, Wk, bk, nullptr, k,  ROWS, Ss, Ss, 0, 0, 0, 0);
    gemm_kernel<<<gproj, 256>>>(sn, Wv, bv, nullptr, vp, ROWS, Ss, Ss, 0, 0, 0, 0);

    // 3) vector channel mix (vn @ Wvv)
    vmix_kernel<<<ROWS, 192>>>(vn, Wvv, vmix);

    // 4) fused attention: writes g_sattn + g_attnmean
    attn_kernel<<<dim3(Nn/32, Bb), 256, attn_smem>>>(q, k, vp, pos, wdist, bdist, am, sa);

    // 5) out_s = s_in + sattn @ Wo + bo
    gemm_kernel<<<gproj, 256>>>(sa, Wo, bo, s_in, out_s, ROWS, Ss, Ss, 2, 0, 0, 0);

    // 6) v_attn_raw = attn_mean @ vmix  (batched over B)
    gemm_kernel<<<dim3(192/64, Nn/64, Bb), 256>>>(
        am, vmix, nullptr, nullptr, va,
        Nn, 192, Nn, 0,
        (long long)Nn*Nn, (long long)Nn*192, (long long)Nn*192);

    // 7) out_v = v_in + v_attn_raw @ Wvo
    vout_kernel<<<ROWS, 192>>>(va, Wvo, v_in, out_v);

    // 8) eq-LN #2 (on updated s, v)
    eqln_kernel<<<ROWS, 256>>>(out_s, out_v, g2, be2, vs2, sn, vn);

    // 9) FFN
    gemm_kernel<<<dim3(Ff/64, ROWS/64, 1), 256>>>(sn, Wf1, bf1, nullptr, ffn, ROWS, Ff, Ss, 1, 0, 0, 0);
    gemm_kernel<<<dim3(Ss/64, ROWS/64, 1), 256>>>(ffn, Wf2, bf2, out_s, out_s, ROWS, Ss, Ff, 2, 0, 0, 0);

    // 10) vector FFN
    vffn_kernel<<<ROWS, 256>>>(vn, Wfv1, Wfv2, out_v);
}

// round 8
// speedup vs baseline: 2.0372x; 2.0276x over previous
#include <cuda_runtime.h>
#include <cuda_bf16.h>
#include <math.h>

#define Bb   4
#define Nn   2048
#define Ss   256
#define Cc   64
#define Hh   4
#define Dd   64
#define Ff   1024
#define ROWS (Bb*Nn)          // 8192

// ---------------- scratch (static device memory; no allocations) -------------
__device__ float g_sn[ROWS*Ss];
__device__ float g_vn[ROWS*Cc*3];
__device__ float g_q[ROWS*Ss];
__device__ float g_k[ROWS*Ss];
__device__ float g_vp[ROWS*Ss];
__device__ float g_vmix[ROWS*Cc*3];
__device__ __nv_bfloat16 g_probs[(size_t)Bb*Hh*Nn*Nn];   // 134 MB unnormalized probs
__device__ float g_linv[(size_t)Bb*Hh*Nn];
__device__ float g_attnmean[(size_t)Bb*Nn*Nn];            // 67 MB
__device__ float g_sattn[ROWS*Ss];
__device__ float g_vattn[ROWS*Cc*3];
__device__ float g_ffn[ROWS*Ff];

// ---------------- eq layernorm ----------------------------------------------
__global__ void __launch_bounds__(256) eqln_kernel(
    const float* __restrict__ sin, const float* __restrict__ vin,
    const float* __restrict__ g, const float* __restrict__ be,
    const float* __restrict__ vsc,
    float* __restrict__ sn, float* __restrict__ vn)
{
    long long row = blockIdx.x;
    int tid = threadIdx.x;
    __shared__ float redA[8], redB[8], norms[64], st[3];

    float x = sin[row*Ss + tid];
    float s1 = x, s2 = x*x;
    #pragma unroll
    for (int o = 16; o; o >>= 1) {
        s1 += __shfl_xor_sync(0xffffffffu, s1, o);
        s2 += __shfl_xor_sync(0xffffffffu, s2, o);
    }
    if ((tid & 31) == 0) { redA[tid>>5] = s1; redB[tid>>5] = s2; }

    if (tid < 64) {
        const float* vp = vin + row*192 + tid*3;
        float a = vp[0], b2 = vp[1], c = vp[2];
        norms[tid] = sqrtf(a*a + b2*b2 + c*c);
    }
    __syncthreads();
    if (tid == 0) {
        float A = 0.f, Bs2 = 0.f;
        #pragma unroll
        for (int w = 0; w < 8; w++) { A += redA[w]; Bs2 += redB[w]; }
        float mu  = A * (1.f/256.f);
        float var = Bs2 * (1.f/256.f) - mu*mu;
        st[0] = mu; st[1] = rsqrtf(var + 1e-5f);
        float t = 0.f;
        for (int c = 0; c < 64; c++) t += norms[c];
        st[2] = t * (1.f/64.f);
    }
    __syncthreads();
    sn[row*Ss + tid] = (x - st[0]) * st[1] * g[tid] + be[tid];
    if (tid < 192) {
        int c = tid / 3;
        vn[row*192 + tid] = vin[row*192 + tid] / (norms[c] + 1e-5f) * st[2] * vsc[c];
    }
}

// ---------------- generic tiled fp32 GEMM -----------------------------------
__global__ void __launch_bounds__(256) gemm_kernel(
    const float* __restrict__ A, const float* __restrict__ W,
    const float* __restrict__ bias, const float* __restrict__ res,
    float* __restrict__ Cout,
    int M, int N, int K, int epi,
    long long sA, long long sW, long long sC)
{
    long long bz = blockIdx.z;
    A += bz * sA; W += bz * sW; Cout += bz * sC;
    const float* resp = res ? res + bz * sC : (const float*)0;

    __shared__ float As[16][68];
    __shared__ float Bs[16][64];

    int tid = threadIdx.x;
    int tx = tid & 15, ty = tid >> 4;
    int m0 = blockIdx.y * 64, n0 = blockIdx.x * 64;

    float acc[4][4] = {};

    for (int k0 = 0; k0 < K; k0 += 16) {
        #pragma unroll
        for (int r = 0; r < 4; r++) {
            int l = tid + r*256;
            int m = l >> 4, kk = l & 15;
            As[kk][m] = A[(long long)(m0+m)*K + k0 + kk];
        }
        #pragma unroll
        for (int r = 0; r < 4; r++) {
            int l = tid + r*256;
            int kk = l >> 6, n = l & 63;
            Bs[kk][n] = W[(long long)(k0+kk)*N + n0 + n];
        }
        __syncthreads();
        #pragma unroll
        for (int k = 0; k < 16; k++) {
            float4 af = *(const float4*)&As[k][ty*4];
            float4 bf = *(const float4*)&Bs[k][tx*4];
            float a[4] = {af.x, af.y, af.z, af.w};
            float b[4] = {bf.x, bf.y, bf.z, bf.w};
            #pragma unroll
            for (int i = 0; i < 4; i++)
                #pragma unroll
                for (int j = 0; j < 4; j++)
                    acc[i][j] += a[i]*b[j];
        }
        __syncthreads();
    }

    #pragma unroll
    for (int i = 0; i < 4; i++) {
        int m = m0 + ty*4 + i;
        #pragma unroll
        for (int j = 0; j < 4; j++) {
            int n = n0 + tx*4 + j;
            float cv = acc[i][j];
            if (bias) cv += bias[n];
            if (epi == 1) {
                cv = 0.5f * cv * (1.0f + erff(cv * 0.70710678118654752f));
            } else if (epi == 2) {
                cv += resp[(long long)m*N + n];
            }
            Cout[(long long)m*N + n] = cv;
        }
    }
}

// ---------------- small per-row channel mixes -------------------------------
__global__ void __launch_bounds__(192) vmix_kernel(
    const float* __restrict__ vn, const float* __restrict__ Wvv, float* __restrict__ out)
{
    long long row = blockIdx.x;
    int tid = threadIdx.x;
    __shared__ float vrow[192];
    vrow[tid] = vn[row*192 + tid];
    __syncthreads();
    int x = tid >> 6, e = tid & 63;
    float acc = 0.f;
    #pragma unroll 8
    for (int c = 0; c < 64; c++) acc += vrow[c*3 + x] * Wvv[c*64 + e];
    out[row*192 + e*3 + x] = acc;
}

__global__ void __launch_bounds__(192) vout_kernel(
    const float* __restrict__ vattn, const float* __restrict__ Wvo,
    const float* __restrict__ vin, float* __restrict__ outv)
{
    long long row = blockIdx.x;
    int tid = threadIdx.x;
    __shared__ float vrow[192];
    vrow[tid] = vattn[row*192 + tid];
    __syncthreads();
    int x = tid >> 6, e = tid & 63;
    float acc = 0.f;
    #pragma unroll 8
    for (int c = 0; c < 64; c++) acc += vrow[c*3 + x] * Wvo[c*64 + e];
    outv[row*192 + e*3 + x] = vin[row*192 + e*3 + x] + acc;
}

__global__ void __launch_bounds__(256) vffn_kernel(
    const float* __restrict__ vn, const float* __restrict__ Wfv1,
    const float* __restrict__ Wfv2, float* __restrict__ outv)
{
    long long row = blockIdx.x;
    int tid = threadIdx.x;
    __shared__ float vrow[192];
    __shared__ float t[3][256];
    if (tid < 192) vrow[tid] = vn[row*192 + tid];
    __syncthreads();
    #pragma unroll
    for (int x = 0; x < 3; x++) {
        float acc = 0.f;
        #pragma unroll 8
        for (int c = 0; c < 64; c++) acc += vrow[c*3 + x] * Wfv1[c*256 + tid];
        t[x][tid] = acc;
    }
    __syncthreads();
    if (tid < 192) {
        int x = tid >> 6, c = tid & 63;
        float acc = 0.f;
        #pragma unroll 8
        for (int h = 0; h < 256; h++) acc += t[x][h] * Wfv2[h*64 + c];
        outv[row*192 + c*3 + x] += acc;
    }
}

// ---------------- fused single-pass attention --------------------------------
// 64 query rows per CTA, 512 threads, all 4 heads per CTA.
// exp(qk/8 - softplus(sx)) = exp(qk/8) / (1 + exp(sx))
// PV accumulated UNNORMALIZED in registers; scaled by 1/rowsum at the end.
// Unnormalized probs -> bf16 gmem; linv -> gmem (consumed by mean_kernel).
#define QT_LD 68
#define KT_LD 36
#define PS_LD 33
#define ATTN_SMEM_FLOATS (256*QT_LD + 256*KT_LD + 8192 + 4*64*PS_LD + 256 + 128 + 256)

__global__ void __launch_bounds__(512) attn_kernel(
    const float* __restrict__ qg, const float* __restrict__ kg,
    const float* __restrict__ vg, const float* __restrict__ pos,
    const float* __restrict__ wdist, const float* __restrict__ bdist,
    __nv_bfloat16* __restrict__ probsG, float* __restrict__ linvG,
    float* __restrict__ sattn)
{
    extern __shared__ float sm[];
    float* qT     = sm;                       // [256][68]  q transposed (d-major)
    float* kT     = qT + 256*QT_LD;           // [256][36]  k transposed (d-major)
    float* v_s    = kT + 256*KT_LD;           // [32][256]
    float* ps     = v_s + 8192;               // [4*64][33] unnormalized p tile
    float* posi   = ps + 4*64*PS_LD;          // [64][4]
    float* posm   = posi + 256;               // [32][4]
    float* linv_s = posm + 128;               // [4][64]

    const int b  = blockIdx.y;
    const int n0 = blockIdx.x * 64;
    const int tid = threadIdx.x;
    const int lane = tid & 31, wrp = tid >> 5;
    const long long bofs = (long long)b * Nn;

    // QK work split: head = tid>>7; within head, 4x4 tile over (i,m)
    const int h   = tid >> 7;
    const int r   = tid & 127;
    const int ti  = r >> 3, tm = r & 7;
    const int i0q = ti*4, m0q = tm*4;
    // PV split: 4 i-rows x 8 v-cols per thread
    const int cv0 = (wrp & 7)*32 + (lane & 3)*8;
    const int i0p = (wrp >> 3)*32 + (lane >> 2)*4;
    const int hp  = (wrp & 7) >> 1;

    for (int idx = tid; idx < 16384; idx += 512) {
        int i = idx >> 8, d = idx & 255;
        qT[d*QT_LD + i] = qg[(bofs + n0 + i)*Ss + d];
    }
    if (tid < 64) {
        const float* pp = pos + (bofs + n0 + tid)*3;
        float a = pp[0], b2 = pp[1], c = pp[2];
        posi[tid*4+0]=a; posi[tid*4+1]=b2; posi[tid*4+2]=c; posi[tid*4+3]=a*a+b2*b2+c*c;
    }
    __syncthreads();

    float4 pi[4];
    #pragma unroll
    for (int ii = 0; ii < 4; ii++) pi[ii] = ((const float4*)posi)[i0q+ii];
    const float wh = wdist[h], bh = bdist[h];

    float accS[32];
    #pragma unroll
    for (int t = 0; t < 32; t++) accS[t] = 0.f;
    float rs[4] = {0.f, 0.f, 0.f, 0.f};

    __nv_bfloat16* pgbase = probsG + ((size_t)(b*4 + h)*Nn + n0)*Nn;
    const float* qb = qT + (h*64)*QT_LD + i0q;
    const float* kb = kT + (h*64)*KT_LD + m0q;

    for (int mt = 0; mt < 64; mt++) {
        const int m0g = mt*32;
        __syncthreads();
        for (int idx = tid; idx < 8192; idx += 512) {
            int m = idx >> 8, d = idx & 255;
            long long grow = (bofs + m0g + m)*Ss + d;
            kT[d*KT_LD + m] = kg[grow];
            v_s[idx] = vg[grow];
        }
        if (tid < 32) {
            const float* pp = pos + (bofs + m0g + tid)*3;
            float a = pp[0], b2 = pp[1], c = pp[2];
            posm[tid*4+0]=a; posm[tid*4+1]=b2; posm[tid*4+2]=c; posm[tid*4+3]=a*a+b2*b2+c*c;
        }
        __syncthreads();

        // ---- QK^T 4x4 register tile ----
        float acc[4][4];
        #pragma unroll
        for (int i = 0; i < 4; i++)
            #pragma unroll
            for (int j = 0; j < 4; j++) acc[i][j] = 0.f;

        #pragma unroll 16
        for (int d = 0; d < 64; d++) {
            float4 qv = *(const float4*)(qb + d*QT_LD);
            float4 kv = *(const float4*)(kb + d*KT_LD);
            float qa[4] = {qv.x, qv.y, qv.z, qv.w};
            float ka[4] = {kv.x, kv.y, kv.z, kv.w};
            #pragma unroll
            for (int i = 0; i < 4; i++)
                #pragma unroll
                for (int j = 0; j < 4; j++)
                    acc[i][j] += qa[i]*ka[j];
        }

        float4 pmv[4];
        #pragma unroll
        for (int mj = 0; mj < 4; mj++) pmv[mj] = ((const float4*)posm)[m0q+mj];

        #pragma unroll
        for (int ii = 0; ii < 4; ii++) {
            float pv[4];
            #pragma unroll
            for (int mj = 0; mj < 4; mj++) {
                float d2 = pi[ii].w + pmv[mj].w
                         - 2.f*(pi[ii].x*pmv[mj].x + pi[ii].y*pmv[mj].y + pi[ii].z*pmv[mj].z);
                float dist = sqrtf(fmaxf(d2, 1e-12f));
                float sx = dist*wh + bh;
                float sg = __fdividef(1.f, 1.f + __expf(sx));   // exp(-softplus(sx))
                float p  = __expf(acc[ii][mj]*0.125f) * sg;
                pv[mj] = p;
                rs[ii] += p;
                ps[(h*64 + i0q + ii)*PS_LD + m0q + mj] = p;
            }
            __nv_bfloat162 p01 = __floats2bfloat162_rn(pv[0], pv[1]);
            __nv_bfloat162 p23 = __floats2bfloat162_rn(pv[2], pv[3]);
            float2 packed = make_float2(__uint_as_float(*(unsigned int*)&p01),
                                        __uint_as_float(*(unsigned int*)&p23));
            __stcs(reinterpret_cast<float2*>(pgbase + (size_t)(i0q+ii)*Nn + m0g + m0q), packed);
        }
        __syncthreads();

        // ---- PV accumulation (unnormalized), 4x8 register tile ----
        #pragma unroll 4
        for (int j = 0; j < 32; j++) {
            float4 v0 = *(const float4*)(v_s + j*256 + cv0);
            float4 v1 = *(const float4*)(v_s + j*256 + cv0 + 4);
            float pj[4];
            #pragma unroll
            for (int ii = 0; ii < 4; ii++)
                pj[ii] = ps[(hp*64 + i0p + ii)*PS_LD + j];
            #pragma unroll
            for (int ii = 0; ii < 4; ii++) {
                accS[ii*8+0] += pj[ii]*v0.x; accS[ii*8+1] += pj[ii]*v0.y;
                accS[ii*8+2] += pj[ii]*v0.z; accS[ii*8+3] += pj[ii]*v0.w;
                accS[ii*8+4] += pj[ii]*v1.x; accS[ii*8+5] += pj[ii]*v1.y;
                accS[ii*8+6] += pj[ii]*v1.z; accS[ii*8+7] += pj[ii]*v1.w;
            }
        }
    }

    // ---- row-sum reduction across the 8 tm lanes sharing a row ----
    #pragma unroll
    for (int ii = 0; ii < 4; ii++) {
        float v = rs[ii];
        v += __shfl_xor_sync(0xffffffffu, v, 1);
        v += __shfl_xor_sync(0xffffffffu, v, 2);
        v += __shfl_xor_sync(0xffffffffu, v, 4);
        rs[ii] = v;
    }
    if ((lane & 7) == 0) {
        #pragma unroll
        for (int ii = 0; ii < 4; ii++) {
            float inv = __fdividef(1.f, rs[ii]);
            linv_s[h*64 + i0q + ii] = inv;
            linvG[(size_t)(b*4 + h)*Nn + n0 + i0q + ii] = inv;
        }
    }
    __syncthreads();

    // ---- normalize + store s_attn ----
    #pragma unroll
    for (int ii = 0; ii < 4; ii++) {
        int i = i0p + ii;
        float li = linv_s[hp*64 + i];
        float4 o0 = make_float4(accS[ii*8+0]*li, accS[ii*8+1]*li, accS[ii*8+2]*li, accS[ii*8+3]*li);
        float4 o1 = make_float4(accS[ii*8+4]*li, accS[ii*8+5]*li, accS[ii*8+6]*li, accS[ii*8+7]*li);
        float* op = sattn + (bofs + n0 + i)*Ss + cv0;
        *(float4*)op = o0;
        *(float4*)(op+4) = o1;
    }
}

// ---------------- attn_mean from bf16 probs + linv ---------------------------
__global__ void __launch_bounds__(512) mean_kernel(
    const __nv_bfloat16* __restrict__ pg, const float* __restrict__ linvG,
    float* __restrict__ am)
{
    const int i = blockIdx.x;
    const int b = blockIdx.y;
    const size_t pstride = (size_t)Nn*Nn;
    const __nv_bfloat16* base = pg + (size_t)b*4*pstride + (size_t)i*Nn;
    const float l0 = 0.25f * linvG[(size_t)(b*4+0)*Nn + i];
    const float l1 = 0.25f * linvG[(size_t)(b*4+1)*Nn + i];
    const float l2 = 0.25f * linvG[(size_t)(b*4+2)*Nn + i];
    const float l3 = 0.25f * linvG[(size_t)(b*4+3)*Nn + i];
    const int j = threadIdx.x * 4;

    float4 o;
    #pragma unroll
    for (int t = 0; t < 2; t++) {
        __nv_bfloat162 a0 = *(const __nv_bfloat162*)(base + j + 2*t);
        __nv_bfloat162 a1 = *(const __nv_bfloat162*)(base + pstride   + j + 2*t);
        __nv_bfloat162 a2 = *(const __nv_bfloat162*)(base + 2*pstride + j + 2*t);
        __nv_bfloat162 a3 = *(const __nv_bfloat162*)(base + 3*pstride + j + 2*t);
        float lo = l0*__low2float(a0)  + l1*__low2float(a1)  + l2*__low2float(a2)  + l3*__low2float(a3);
        float hi = l0*__high2float(a0) + l1*__high2float(a1) + l2*__high2float(a2) + l3*__high2float(a3);
        if (t == 0) { o.x = lo; o.y = hi; } else { o.z = lo; o.w = hi; }
    }
    *reinterpret_cast<float4*>(am + ((size_t)b*Nn + i)*Nn + j) = o;
}

// ---------------- launch ------------------------------------------------------
extern "C" void kernel_launch(void* const* d_in, const int* in_sizes, int n_in,
                              void* d_out, int out_size)
{
    const float* s_in  = (const float*)d_in[0];
    const float* v_in  = (const float*)d_in[1];
    const float* pos   = (const float*)d_in[2];
    const float* Wq    = (const float*)d_in[3];
    const float* bq    = (const float*)d_in[4];
    const float* Wk    = (const float*)d_in[5];
    const float* bk    = (const float*)d_in[6];
    const float* Wv    = (const float*)d_in[7];
    const float* bv    = (const float*)d_in[8];
    const float* Wo    = (const float*)d_in[9];
    const float* bo    = (const float*)d_in[10];
    const float* wdist = (const float*)d_in[11];
    const float* bdist = (const float*)d_in[12];
    const float* Wvv   = (const float*)d_in[13];
    const float* Wvo   = (const float*)d_in[14];
    const float* g1    = (const float*)d_in[15];
    const float* be1   = (const float*)d_in[16];
    const float* vs1   = (const float*)d_in[17];
    const float* g2    = (const float*)d_in[18];
    const float* be2   = (const float*)d_in[19];
    const float* vs2   = (const float*)d_in[20];
    const float* Wf1   = (const float*)d_in[21];
    const float* bf1   = (const float*)d_in[22];
    const float* Wf2   = (const float*)d_in[23];
    const float* bf2   = (const float*)d_in[24];
    const float* Wfv1  = (const float*)d_in[25];
    const float* Wfv2  = (const float*)d_in[26];

    float* out_s = (float*)d_out;
    float* out_v = out_s + (size_t)ROWS*Ss;

    void *p_sn, *p_vn, *p_q, *p_k, *p_vp, *p_vmix, *p_pb, *p_li, *p_am, *p_sa, *p_va, *p_ffn;
    cudaGetSymbolAddress(&p_sn, g_sn);
    cudaGetSymbolAddress(&p_vn, g_vn);
    cudaGetSymbolAddress(&p_q,  g_q);
    cudaGetSymbolAddress(&p_k,  g_k);
    cudaGetSymbolAddress(&p_vp, g_vp);
    cudaGetSymbolAddress(&p_vmix, g_vmix);
    cudaGetSymbolAddress(&p_pb, g_probs);
    cudaGetSymbolAddress(&p_li, g_linv);
    cudaGetSymbolAddress(&p_am, g_attnmean);
    cudaGetSymbolAddress(&p_sa, g_sattn);
    cudaGetSymbolAddress(&p_va, g_vattn);
    cudaGetSymbolAddress(&p_ffn, g_ffn);
    float* sn   = (float*)p_sn;   float* vn   = (float*)p_vn;
    float* q    = (float*)p_q;    float* k    = (float*)p_k;
    float* vp   = (float*)p_vp;   float* vmix = (float*)p_vmix;
    __nv_bfloat16* pb = (__nv_bfloat16*)p_pb;
    float* li   = (float*)p_li;   float* am   = (float*)p_am;
    float* sa   = (float*)p_sa;   float* va   = (float*)p_va;
    float* ffn  = (float*)p_ffn;

    const int attn_smem = ATTN_SMEM_FLOATS * 4;
    cudaFuncSetAttribute(attn_kernel, cudaFuncAttributeMaxDynamicSharedMemorySize, attn_smem);

    // 1) eq-LN #1
    eqln_kernel<<<ROWS, 256>>>(s_in, v_in, g1, be1, vs1, sn, vn);

    // 2) QKV projections
    dim3 gproj(Ss/64, ROWS/64, 1);
    gemm_kernel<<<gproj, 256>>>(sn, Wq, bq, nullptr, q,  ROWS, Ss, Ss, 0, 0, 0, 0);
    gemm_kernel<<<gproj, 256>>>(sn, Wk, bk, nullptr, k,  ROWS, Ss, Ss, 0, 0, 0, 0);
    gemm_kernel<<<gproj, 256>>>(sn, Wv, bv, nullptr, vp, ROWS, Ss, Ss, 0, 0, 0, 0);

    // 3) vector channel mix (vn @ Wvv)
    vmix_kernel<<<ROWS, 192>>>(vn, Wvv, vmix);

    // 4) fused single-pass attention -> sattn, bf16 probs, linv
    attn_kernel<<<dim3(Nn/64, Bb), 512, attn_smem>>>(q, k, vp, pos, wdist, bdist, pb, li, sa);

    // 5) attn_mean from probs + linv
    mean_kernel<<<dim3(Nn, Bb), 512>>>(pb, li, am);

    // 6) out_s = s_in + sattn @ Wo + bo
    gemm_kernel<<<gproj, 256>>>(sa, Wo, bo, s_in, out_s, ROWS, Ss, Ss, 2, 0, 0, 0);

    // 7) v_attn_raw = attn_mean @ vmix  (batched over B)
    gemm_kernel<<<dim3(192/64, Nn/64, Bb), 256>>>(
        am, vmix, nullptr, nullptr, va,
        Nn, 192, Nn, 0,
        (long long)Nn*Nn, (long long)Nn*192, (long long)Nn*192);

    // 8) out_v = v_in + v_attn_raw @ Wvo
    vout_kernel<<<ROWS, 192>>>(va, Wvo, v_in, out_v);

    // 9) eq-LN #2
    eqln_kernel<<<ROWS, 256>>>(out_s, out_v, g2, be2, vs2, sn, vn);

    // 10) FFN
    gemm_kernel<<<dim3(Ff/64, ROWS/64, 1), 256>>>(sn, Wf1, bf1, nullptr, ffn, ROWS, Ff, Ss, 1, 0, 0, 0);
    gemm_kernel<<<dim3(Ss/64, ROWS/64, 1), 256>>>(ffn, Wf2, bf2, out_s, out_s, ROWS, Ss, Ff, 2, 0, 0, 0);

    // 11) vector FFN
    vffn_kernel<<<ROWS, 256>>>(vn, Wfv1, Wfv2, out_v);
}

// round 9
// speedup vs baseline: 2.1868x; 1.0734x over previous
#include <cuda_runtime.h>
#include <cuda_bf16.h>
#include <math.h>

#define Bb   4
#define Nn   2048
#define Ss   256
#define Cc   64
#define Hh   4
#define Dd   64
#define Ff   1024
#define ROWS (Bb*Nn)          // 8192

// ---------------- scratch (static device memory; no allocations) -------------
__device__ float g_sn[ROWS*Ss];
__device__ float g_vn[ROWS*Cc*3];
__device__ float g_q[ROWS*Ss];
__device__ float g_k[ROWS*Ss];
__device__ float g_vp[ROWS*Ss];
__device__ float g_vmix[ROWS*Cc*3];
__device__ __nv_bfloat16 g_probs[(size_t)Bb*Hh*Nn*Nn];   // 134 MB unnormalized probs
__device__ float g_linv[(size_t)Bb*Hh*Nn];
__device__ float g_attnmean[(size_t)Bb*Nn*Nn];            // 67 MB
__device__ float g_sattn[ROWS*Ss];
__device__ float g_vattn[ROWS*Cc*3];
__device__ float g_ffn[ROWS*Ff];

// ---------------- eq layernorm ----------------------------------------------
__global__ void __launch_bounds__(256) eqln_kernel(
    const float* __restrict__ sin, const float* __restrict__ vin,
    const float* __restrict__ g, const float* __restrict__ be,
    const float* __restrict__ vsc,
    float* __restrict__ sn, float* __restrict__ vn)
{
    long long row = blockIdx.x;
    int tid = threadIdx.x;
    __shared__ float redA[8], redB[8], norms[64], st[3];

    float x = sin[row*Ss + tid];
    float s1 = x, s2 = x*x;
    #pragma unroll
    for (int o = 16; o; o >>= 1) {
        s1 += __shfl_xor_sync(0xffffffffu, s1, o);
        s2 += __shfl_xor_sync(0xffffffffu, s2, o);
    }
    if ((tid & 31) == 0) { redA[tid>>5] = s1; redB[tid>>5] = s2; }

    if (tid < 64) {
        const float* vp = vin + row*192 + tid*3;
        float a = vp[0], b2 = vp[1], c = vp[2];
        norms[tid] = sqrtf(a*a + b2*b2 + c*c);
    }
    __syncthreads();
    if (tid == 0) {
        float A = 0.f, Bs2 = 0.f;
        #pragma unroll
        for (int w = 0; w < 8; w++) { A += redA[w]; Bs2 += redB[w]; }
        float mu  = A * (1.f/256.f);
        float var = Bs2 * (1.f/256.f) - mu*mu;
        st[0] = mu; st[1] = rsqrtf(var + 1e-5f);
        float t = 0.f;
        for (int c = 0; c < 64; c++) t += norms[c];
        st[2] = t * (1.f/64.f);
    }
    __syncthreads();
    sn[row*Ss + tid] = (x - st[0]) * st[1] * g[tid] + be[tid];
    if (tid < 192) {
        int c = tid / 3;
        vn[row*192 + tid] = vin[row*192 + tid] / (norms[c] + 1e-5f) * st[2] * vsc[c];
    }
}

// ---------------- tiled fp32 GEMM: 128x64 CTA tile, 8x4 per thread ----------
// C[m,n] = epi( A[m,:] @ W[:,n] + bias[n] (+ res[m,n]) )
// Requirements: M % 128 == 0, N % 64 == 0, K % 16 == 0.
#define GBM 128
#define GBN 64
#define GBK 16

__global__ void __launch_bounds__(256) gemm_kernel(
    const float* __restrict__ A, const float* __restrict__ W,
    const float* __restrict__ bias, const float* __restrict__ res,
    float* __restrict__ Cout,
    int M, int N, int K, int epi,
    long long sA, long long sW, long long sC)
{
    long long bz = blockIdx.z;
    A += bz * sA; W += bz * sW; Cout += bz * sC;
    const float* resp = res ? res + bz * sC : (const float*)0;

    __shared__ float As[2][GBK][GBM+4];   // [k][m], transposed
    __shared__ float Bs[2][GBK][GBN+4];   // [k][n]

    const int tid = threadIdx.x;
    const int tx = tid & 15, ty = tid >> 4;
    const int m0 = blockIdx.y * GBM, n0 = blockIdx.x * GBN;

    // global-load decomposition
    const int arow = tid >> 2;           // 0..63
    const int akk  = (tid & 3) * 4;      // 0,4,8,12
    const int brow = tid >> 4;           // 0..15
    const int bn4  = (tid & 15) * 4;

    const float* Aptr = A + (long long)(m0 + arow)*K + akk;
    const float* Wptr = W + (long long)brow*N + n0 + bn4;
    const long long a64 = (long long)64*K;

    float4 ra0 = *(const float4*)(Aptr);
    float4 ra1 = *(const float4*)(Aptr + a64);
    float4 rb  = *(const float4*)(Wptr);

    As[0][akk+0][arow] = ra0.x; As[0][akk+1][arow] = ra0.y;
    As[0][akk+2][arow] = ra0.z; As[0][akk+3][arow] = ra0.w;
    As[0][akk+0][arow+64] = ra1.x; As[0][akk+1][arow+64] = ra1.y;
    As[0][akk+2][arow+64] = ra1.z; As[0][akk+3][arow+64] = ra1.w;
    *(float4*)&Bs[0][brow][bn4] = rb;
    __syncthreads();

    float acc[8][4];
    #pragma unroll
    for (int i = 0; i < 8; i++)
        #pragma unroll
        for (int j = 0; j < 4; j++) acc[i][j] = 0.f;

    int buf = 0;
    for (int k0 = 0; k0 < K; k0 += GBK) {
        const bool has_next = (k0 + GBK) < K;
        if (has_next) {
            ra0 = *(const float4*)(Aptr + k0 + GBK);
            ra1 = *(const float4*)(Aptr + a64 + k0 + GBK);
            rb  = *(const float4*)(Wptr + (long long)(k0 + GBK)*N);
        }
        #pragma unroll
        for (int k = 0; k < GBK; k++) {
            float4 af0 = *(const float4*)&As[buf][k][ty*8];
            float4 af1 = *(const float4*)&As[buf][k][ty*8+4];
            float4 bf  = *(const float4*)&Bs[buf][k][tx*4];
            float a[8] = {af0.x,af0.y,af0.z,af0.w,af1.x,af1.y,af1.z,af1.w};
            float b[4] = {bf.x,bf.y,bf.z,bf.w};
            #pragma unroll
            for (int i = 0; i < 8; i++)
                #pragma unroll
                for (int j = 0; j < 4; j++)
                    acc[i][j] += a[i]*b[j];
        }
        if (has_next) {
            int nb = buf ^ 1;
            As[nb][akk+0][arow] = ra0.x; As[nb][akk+1][arow] = ra0.y;
            As[nb][akk+2][arow] = ra0.z; As[nb][akk+3][arow] = ra0.w;
            As[nb][akk+0][arow+64] = ra1.x; As[nb][akk+1][arow+64] = ra1.y;
            As[nb][akk+2][arow+64] = ra1.z; As[nb][akk+3][arow+64] = ra1.w;
            *(float4*)&Bs[nb][brow][bn4] = rb;
        }
        __syncthreads();
        buf ^= 1;
    }

    // epilogue
    float bv[4];
    if (bias) {
        #pragma unroll
        for (int j = 0; j < 4; j++) bv[j] = bias[n0 + tx*4 + j];
    } else {
        #pragma unroll
        for (int j = 0; j < 4; j++) bv[j] = 0.f;
    }
    #pragma unroll
    for (int i = 0; i < 8; i++) {
        int m = m0 + ty*8 + i;
        long long off = (long long)m*N + n0 + tx*4;
        float4 o;
        float c0 = acc[i][0]+bv[0], c1 = acc[i][1]+bv[1];
        float c2 = acc[i][2]+bv[2], c3 = acc[i][3]+bv[3];
        if (epi == 1) {
            c0 = 0.5f*c0*(1.0f + erff(c0*0.70710678118654752f));
            c1 = 0.5f*c1*(1.0f + erff(c1*0.70710678118654752f));
            c2 = 0.5f*c2*(1.0f + erff(c2*0.70710678118654752f));
            c3 = 0.5f*c3*(1.0f + erff(c3*0.70710678118654752f));
        } else if (epi == 2) {
            float4 rr = *(const float4*)(resp + off);
            c0 += rr.x; c1 += rr.y; c2 += rr.z; c3 += rr.w;
        }
        o.x = c0; o.y = c1; o.z = c2; o.w = c3;
        *(float4*)(Cout + off) = o;
    }
}

// ---------------- small per-row channel mixes -------------------------------
__global__ void __launch_bounds__(192) vmix_kernel(
    const float* __restrict__ vn, const float* __restrict__ Wvv, float* __restrict__ out)
{
    long long row = blockIdx.x;
    int tid = threadIdx.x;
    __shared__ float vrow[192];
    vrow[tid] = vn[row*192 + tid];
    __syncthreads();
    int x = tid >> 6, e = tid & 63;
    float acc = 0.f;
    #pragma unroll 8
    for (int c = 0; c < 64; c++) acc += vrow[c*3 + x] * Wvv[c*64 + e];
    out[row*192 + e*3 + x] = acc;
}

__global__ void __launch_bounds__(192) vout_kernel(
    const float* __restrict__ vattn, const float* __restrict__ Wvo,
    const float* __restrict__ vin, float* __restrict__ outv)
{
    long long row = blockIdx.x;
    int tid = threadIdx.x;
    __shared__ float vrow[192];
    vrow[tid] = vattn[row*192 + tid];
    __syncthreads();
    int x = tid >> 6, e = tid & 63;
    float acc = 0.f;
    #pragma unroll 8
    for (int c = 0; c < 64; c++) acc += vrow[c*3 + x] * Wvo[c*64 + e];
    outv[row*192 + e*3 + x] = vin[row*192 + e*3 + x] + acc;
}

__global__ void __launch_bounds__(256) vffn_kernel(
    const float* __restrict__ vn, const float* __restrict__ Wfv1,
    const float* __restrict__ Wfv2, float* __restrict__ outv)
{
    long long row = blockIdx.x;
    int tid = threadIdx.x;
    __shared__ float vrow[192];
    __shared__ float t[3][256];
    if (tid < 192) vrow[tid] = vn[row*192 + tid];
    __syncthreads();
    #pragma unroll
    for (int x = 0; x < 3; x++) {
        float acc = 0.f;
        #pragma unroll 8
        for (int c = 0; c < 64; c++) acc += vrow[c*3 + x] * Wfv1[c*256 + tid];
        t[x][tid] = acc;
    }
    __syncthreads();
    if (tid < 192) {
        int x = tid >> 6, c = tid & 63;
        float acc = 0.f;
        #pragma unroll 8
        for (int h = 0; h < 256; h++) acc += t[x][h] * Wfv2[h*64 + c];
        outv[row*192 + c*3 + x] += acc;
    }
}

// ---------------- fused single-pass attention --------------------------------
#define QT_LD 68
#define KT_LD 36
#define PS_LD 33
#define ATTN_SMEM_FLOATS (256*QT_LD + 256*KT_LD + 8192 + 4*64*PS_LD + 256 + 128 + 256)

__global__ void __launch_bounds__(512) attn_kernel(
    const float* __restrict__ qg, const float* __restrict__ kg,
    const float* __restrict__ vg, const float* __restrict__ pos,
    const float* __restrict__ wdist, const float* __restrict__ bdist,
    __nv_bfloat16* __restrict__ probsG, float* __restrict__ linvG,
    float* __restrict__ sattn)
{
    extern __shared__ float sm[];
    float* qT     = sm;                       // [256][68]
    float* kT     = qT + 256*QT_LD;           // [256][36]
    float* v_s    = kT + 256*KT_LD;           // [32][256]
    float* ps     = v_s + 8192;               // [4*64][33]
    float* posi   = ps + 4*64*PS_LD;          // [64][4]
    float* posm   = posi + 256;               // [32][4]
    float* linv_s = posm + 128;               // [4][64]

    const int b  = blockIdx.y;
    const int n0 = blockIdx.x * 64;
    const int tid = threadIdx.x;
    const int lane = tid & 31, wrp = tid >> 5;
    const long long bofs = (long long)b * Nn;

    const int h   = tid >> 7;
    const int r   = tid & 127;
    const int ti  = r >> 3, tm = r & 7;
    const int i0q = ti*4, m0q = tm*4;
    const int cv0 = (wrp & 7)*32 + (lane & 3)*8;
    const int i0p = (wrp >> 3)*32 + (lane >> 2)*4;
    const int hp  = (wrp & 7) >> 1;

    for (int idx = tid; idx < 16384; idx += 512) {
        int i = idx >> 8, d = idx & 255;
        qT[d*QT_LD + i] = qg[(bofs + n0 + i)*Ss + d];
    }
    if (tid < 64) {
        const float* pp = pos + (bofs + n0 + tid)*3;
        float a = pp[0], b2 = pp[1], c = pp[2];
        posi[tid*4+0]=a; posi[tid*4+1]=b2; posi[tid*4+2]=c; posi[tid*4+3]=a*a+b2*b2+c*c;
    }
    __syncthreads();

    float4 pi[4];
    #pragma unroll
    for (int ii = 0; ii < 4; ii++) pi[ii] = ((const float4*)posi)[i0q+ii];
    const float wh = wdist[h], bh = bdist[h];

    float accS[32];
    #pragma unroll
    for (int t = 0; t < 32; t++) accS[t] = 0.f;
    float rs[4] = {0.f, 0.f, 0.f, 0.f};

    __nv_bfloat16* pgbase = probsG + ((size_t)(b*4 + h)*Nn + n0)*Nn;
    const float* qb = qT + (h*64)*QT_LD + i0q;
    const float* kb = kT + (h*64)*KT_LD + m0q;

    for (int mt = 0; mt < 64; mt++) {
        const int m0g = mt*32;
        __syncthreads();
        for (int idx = tid; idx < 8192; idx += 512) {
            int m = idx >> 8, d = idx & 255;
            long long grow = (bofs + m0g + m)*Ss + d;
            kT[d*KT_LD + m] = kg[grow];
            v_s[idx] = vg[grow];
        }
        if (tid < 32) {
            const float* pp = pos + (bofs + m0g + tid)*3;
            float a = pp[0], b2 = pp[1], c = pp[2];
            posm[tid*4+0]=a; posm[tid*4+1]=b2; posm[tid*4+2]=c; posm[tid*4+3]=a*a+b2*b2+c*c;
        }
        __syncthreads();

        float acc[4][4];
        #pragma unroll
        for (int i = 0; i < 4; i++)
            #pragma unroll
            for (int j = 0; j < 4; j++) acc[i][j] = 0.f;

        #pragma unroll 16
        for (int d = 0; d < 64; d++) {
            float4 qv = *(const float4*)(qb + d*QT_LD);
            float4 kv = *(const float4*)(kb + d*KT_LD);
            float qa[4] = {qv.x, qv.y, qv.z, qv.w};
            float ka[4] = {kv.x, kv.y, kv.z, kv.w};
            #pragma unroll
            for (int i = 0; i < 4; i++)
                #pragma unroll
                for (int j = 0; j < 4; j++)
                    acc[i][j] += qa[i]*ka[j];
        }

        float4 pmv[4];
        #pragma unroll
        for (int mj = 0; mj < 4; mj++) pmv[mj] = ((const float4*)posm)[m0q+mj];

        #pragma unroll
        for (int ii = 0; ii < 4; ii++) {
            float pv[4];
            #pragma unroll
            for (int mj = 0; mj < 4; mj++) {
                float d2 = pi[ii].w + pmv[mj].w
                         - 2.f*(pi[ii].x*pmv[mj].x + pi[ii].y*pmv[mj].y + pi[ii].z*pmv[mj].z);
                float dist = sqrtf(fmaxf(d2, 1e-12f));
                float sx = dist*wh + bh;
                float sg = __fdividef(1.f, 1.f + __expf(sx));
                float p  = __expf(acc[ii][mj]*0.125f) * sg;
                pv[mj] = p;
                rs[ii] += p;
                ps[(h*64 + i0q + ii)*PS_LD + m0q + mj] = p;
            }
            __nv_bfloat162 p01 = __floats2bfloat162_rn(pv[0], pv[1]);
            __nv_bfloat162 p23 = __floats2bfloat162_rn(pv[2], pv[3]);
            float2 packed = make_float2(__uint_as_float(*(unsigned int*)&p01),
                                        __uint_as_float(*(unsigned int*)&p23));
            __stcs(reinterpret_cast<float2*>(pgbase + (size_t)(i0q+ii)*Nn + m0g + m0q), packed);
        }
        __syncthreads();

        #pragma unroll 4
        for (int j = 0; j < 32; j++) {
            float4 v0 = *(const float4*)(v_s + j*256 + cv0);
            float4 v1 = *(const float4*)(v_s + j*256 + cv0 + 4);
            float pj[4];
            #pragma unroll
            for (int ii = 0; ii < 4; ii++)
                pj[ii] = ps[(hp*64 + i0p + ii)*PS_LD + j];
            #pragma unroll
            for (int ii = 0; ii < 4; ii++) {
                accS[ii*8+0] += pj[ii]*v0.x; accS[ii*8+1] += pj[ii]*v0.y;
                accS[ii*8+2] += pj[ii]*v0.z; accS[ii*8+3] += pj[ii]*v0.w;
                accS[ii*8+4] += pj[ii]*v1.x; accS[ii*8+5] += pj[ii]*v1.y;
                accS[ii*8+6] += pj[ii]*v1.z; accS[ii*8+7] += pj[ii]*v1.w;
            }
        }
    }

    #pragma unroll
    for (int ii = 0; ii < 4; ii++) {
        float v = rs[ii];
        v += __shfl_xor_sync(0xffffffffu, v, 1);
        v += __shfl_xor_sync(0xffffffffu, v, 2);
        v += __shfl_xor_sync(0xffffffffu, v, 4);
        rs[ii] = v;
    }
    if ((lane & 7) == 0) {
        #pragma unroll
        for (int ii = 0; ii < 4; ii++) {
            float inv = __fdividef(1.f, rs[ii]);
            linv_s[h*64 + i0q + ii] = inv;
            linvG[(size_t)(b*4 + h)*Nn + n0 + i0q + ii] = inv;
        }
    }
    __syncthreads();

    #pragma unroll
    for (int ii = 0; ii < 4; ii++) {
        int i = i0p + ii;
        float li = linv_s[hp*64 + i];
        float4 o0 = make_float4(accS[ii*8+0]*li, accS[ii*8+1]*li, accS[ii*8+2]*li, accS[ii*8+3]*li);
        float4 o1 = make_float4(accS[ii*8+4]*li, accS[ii*8+5]*li, accS[ii*8+6]*li, accS[ii*8+7]*li);
        float* op = sattn + (bofs + n0 + i)*Ss + cv0;
        *(float4*)op = o0;
        *(float4*)(op+4) = o1;
    }
}

// ---------------- attn_mean from bf16 probs + linv ---------------------------
__global__ void __launch_bounds__(512) mean_kernel(
    const __nv_bfloat16* __restrict__ pg, const float* __restrict__ linvG,
    float* __restrict__ am)
{
    const int i = blockIdx.x;
    const int b = blockIdx.y;
    const size_t pstride = (size_t)Nn*Nn;
    const __nv_bfloat16* base = pg + (size_t)b*4*pstride + (size_t)i*Nn;
    const float l0 = 0.25f * linvG[(size_t)(b*4+0)*Nn + i];
    const float l1 = 0.25f * linvG[(size_t)(b*4+1)*Nn + i];
    const float l2 = 0.25f * linvG[(size_t)(b*4+2)*Nn + i];
    const float l3 = 0.25f * linvG[(size_t)(b*4+3)*Nn + i];
    const int j = threadIdx.x * 4;

    float4 o;
    #pragma unroll
    for (int t = 0; t < 2; t++) {
        __nv_bfloat162 a0 = *(const __nv_bfloat162*)(base + j + 2*t);
        __nv_bfloat162 a1 = *(const __nv_bfloat162*)(base + pstride   + j + 2*t);
        __nv_bfloat162 a2 = *(const __nv_bfloat162*)(base + 2*pstride + j + 2*t);
        __nv_bfloat162 a3 = *(const __nv_bfloat162*)(base + 3*pstride + j + 2*t);
        float lo = l0*__low2float(a0)  + l1*__low2float(a1)  + l2*__low2float(a2)  + l3*__low2float(a3);
        float hi = l0*__high2float(a0) + l1*__high2float(a1) + l2*__high2float(a2) + l3*__high2float(a3);
        if (t == 0) { o.x = lo; o.y = hi; } else { o.z = lo; o.w = hi; }
    }
    *reinterpret_cast<float4*>(am + ((size_t)b*Nn + i)*Nn + j) = o;
}

// ---------------- launch ------------------------------------------------------
extern "C" void kernel_launch(void* const* d_in, const int* in_sizes, int n_in,
                              void* d_out, int out_size)
{
    const float* s_in  = (const float*)d_in[0];
    const float* v_in  = (const float*)d_in[1];
    const float* pos   = (const float*)d_in[2];
    const float* Wq    = (const float*)d_in[3];
    const float* bq    = (const float*)d_in[4];
    const float* Wk    = (const float*)d_in[5];
    const float* bk    = (const float*)d_in[6];
    const float* Wv    = (const float*)d_in[7];
    const float* bv    = (const float*)d_in[8];
    const float* Wo    = (const float*)d_in[9];
    const float* bo    = (const float*)d_in[10];
    const float* wdist = (const float*)d_in[11];
    const float* bdist = (const float*)d_in[12];
    const float* Wvv   = (const float*)d_in[13];
    const float* Wvo   = (const float*)d_in[14];
    const float* g1    = (const float*)d_in[15];
    const float* be1   = (const float*)d_in[16];
    const float* vs1   = (const float*)d_in[17];
    const float* g2    = (const float*)d_in[18];
    const float* be2   = (const float*)d_in[19];
    const float* vs2   = (const float*)d_in[20];
    const float* Wf1   = (const float*)d_in[21];
    const float* bf1   = (const float*)d_in[22];
    const float* Wf2   = (const float*)d_in[23];
    const float* bf2   = (const float*)d_in[24];
    const float* Wfv1  = (const float*)d_in[25];
    const float* Wfv2  = (const float*)d_in[26];

    float* out_s = (float*)d_out;
    float* out_v = out_s + (size_t)ROWS*Ss;

    void *p_sn, *p_vn, *p_q, *p_k, *p_vp, *p_vmix, *p_pb, *p_li, *p_am, *p_sa, *p_va, *p_ffn;
    cudaGetSymbolAddress(&p_sn, g_sn);
    cudaGetSymbolAddress(&p_vn, g_vn);
    cudaGetSymbolAddress(&p_q,  g_q);
    cudaGetSymbolAddress(&p_k,  g_k);
    cudaGetSymbolAddress(&p_vp, g_vp);
    cudaGetSymbolAddress(&p_vmix, g_vmix);
    cudaGetSymbolAddress(&p_pb, g_probs);
    cudaGetSymbolAddress(&p_li, g_linv);
    cudaGetSymbolAddress(&p_am, g_attnmean);
    cudaGetSymbolAddress(&p_sa, g_sattn);
    cudaGetSymbolAddress(&p_va, g_vattn);
    cudaGetSymbolAddress(&p_ffn, g_ffn);
    float* sn   = (float*)p_sn;   float* vn   = (float*)p_vn;
    float* q    = (float*)p_q;    float* k    = (float*)p_k;
    float* vp   = (float*)p_vp;   float* vmix = (float*)p_vmix;
    __nv_bfloat16* pb = (__nv_bfloat16*)p_pb;
    float* li   = (float*)p_li;   float* am   = (float*)p_am;
    float* sa   = (float*)p_sa;   float* va   = (float*)p_va;
    float* ffn  = (float*)p_ffn;

    const int attn_smem = ATTN_SMEM_FLOATS * 4;
    cudaFuncSetAttribute(attn_kernel, cudaFuncAttributeMaxDynamicSharedMemorySize, attn_smem);

    // 1) eq-LN #1
    eqln_kernel<<<ROWS, 256>>>(s_in, v_in, g1, be1, vs1, sn, vn);

    // 2) QKV projections
    dim3 gproj(Ss/GBN, ROWS/GBM, 1);
    gemm_kernel<<<gproj, 256>>>(sn, Wq, bq, nullptr, q,  ROWS, Ss, Ss, 0, 0, 0, 0);
    gemm_kernel<<<gproj, 256>>>(sn, Wk, bk, nullptr, k,  ROWS, Ss, Ss, 0, 0, 0, 0);
    gemm_kernel<<<gproj, 256>>>(sn, Wv, bv, nullptr, vp, ROWS, Ss, Ss, 0, 0, 0, 0);

    // 3) vector channel mix (vn @ Wvv)
    vmix_kernel<<<ROWS, 192>>>(vn, Wvv, vmix);

    // 4) fused single-pass attention -> sattn, bf16 probs, linv
    attn_kernel<<<dim3(Nn/64, Bb), 512, attn_smem>>>(q, k, vp, pos, wdist, bdist, pb, li, sa);

    // 5) attn_mean from probs + linv
    mean_kernel<<<dim3(Nn, Bb), 512>>>(pb, li, am);

    // 6) out_s = s_in + sattn @ Wo + bo
    gemm_kernel<<<gproj, 256>>>(sa, Wo, bo, s_in, out_s, ROWS, Ss, Ss, 2, 0, 0, 0);

    // 7) v_attn_raw = attn_mean @ vmix  (batched over B)
    gemm_kernel<<<dim3(192/GBN, Nn/GBM, Bb), 256>>>(
        am, vmix, nullptr, nullptr, va,
        Nn, 192, Nn, 0,
        (long long)Nn*Nn, (long long)Nn*192, (long long)Nn*192);

    // 8) out_v = v_in + v_attn_raw @ Wvo
    vout_kernel<<<ROWS, 192>>>(va, Wvo, v_in, out_v);

    // 9) eq-LN #2
    eqln_kernel<<<ROWS, 256>>>(out_s, out_v, g2, be2, vs2, sn, vn);

    // 10) FFN
    gemm_kernel<<<dim3(Ff/GBN, ROWS/GBM, 1), 256>>>(sn, Wf1, bf1, nullptr, ffn, ROWS, Ff, Ss, 1, 0, 0, 0);
    gemm_kernel<<<dim3(Ss/GBN, ROWS/GBM, 1), 256>>>(ffn, Wf2, bf2, out_s, out_s, ROWS, Ss, Ff, 2, 0, 0, 0);

    // 11) vector FFN
    vffn_kernel<<<ROWS, 256>>>(vn, Wfv1, Wfv2, out_v);
}